// round 2
// baseline (speedup 1.0000x reference)
#include <cuda_runtime.h>
#include <math.h>

#define NE 200000
#define NN 10000

// ---------------- scratch (static device arrays; no allocation) ----------------
__device__ float gS[NN * 128];                 // node scalar up-proj
__device__ float gV[NN * 384];                 // node vector up-proj, layout [n][m][u]
__device__ float gHa[NE * 64];                 // MLP ping
__device__ float gHb[NE * 64];                 // MLP pong
__device__ float gT[(size_t)NE * 512];         // tpw
__device__ float gSCAL[(size_t)NE * 256];      // [e][k]
__device__ float gVEC[(size_t)NE * 768];       // [e][m][v]
__device__ float gCST;                         // SILU_CST
__device__ int   gIdx64;                       // 1 if edge_index is int64, 0 if int32

// ---------------- f32x2 helpers (FFMA2: 2x fp32 throughput on sm_103a) ---------
__device__ __forceinline__ unsigned long long pk2(float x) {
    unsigned long long r; unsigned u = __float_as_uint(x);
    asm("mov.b64 %0, {%1, %1};" : "=l"(r) : "r"(u));
    return r;
}
__device__ __forceinline__ void ffma2(unsigned long long& d, unsigned long long a,
                                      unsigned long long b) {
    asm("fma.rn.f32x2 %0, %1, %2, %0;" : "+l"(d) : "l"(a), "l"(b));
}
__device__ __forceinline__ float2 upk(unsigned long long v) {
    unsigned lo, hi;
    asm("mov.b64 {%0, %1}, %2;" : "=r"(lo), "=r"(hi) : "l"(v));
    return make_float2(__uint_as_float(lo), __uint_as_float(hi));
}

// ---------------- edge_index dtype detector ------------------------------------
// int64 data read as int32: odd words are high halves == 0 (values < 2^31).
// int32 data: odd words are random node ids; all-zero chance over 128 ~ 0.
__global__ void detect_idx_kernel(const int* __restrict__ idx32) {
    if (threadIdx.x == 0) {
        int any = 0;
        for (int i = 1; i < 256; i += 2) any |= (idx32[i] != 0);
        gIdx64 = (any == 0) ? 1 : 0;
    }
}

// ---------------- SILU_CST: trapezoid integral identical to the reference ------
__global__ void cst_kernel() {
    __shared__ double red[256];
    int t = threadIdx.x;
    double acc = 0.0;
    for (int j = t; j <= 200000; j += 256) {
        double z = -12.0 + 24.0 * ((double)j / 200000.0);
        double pdf = exp(-0.5 * z * z) * 0.39894228040143267794;
        double s = z / (1.0 + exp(-z));
        double f = s * s * pdf;
        if (j == 0 || j == 200000) f *= 0.5;
        acc += f;
    }
    red[t] = acc;
    __syncthreads();
    for (int o = 128; o > 0; o >>= 1) {
        if (t < o) red[t] += red[t + o];
        __syncthreads();
    }
    if (t == 0) {
        double I = red[0] * (24.0 / 200000.0);
        gCST = (float)(1.0 / sqrt(I));
    }
}

// ---------------- generic register-tiled GEMM, FFMA2 inner loop ----------------
// C[r][c] = scale * sum_k A[r][k] * B[k][c]   (+ optional silu*CST epilogue)
// A element: A[r*lda + offA + k*sA]  (VECA=true requires sA==1, K%4==0)
// B element: B[k*ldb + c]           (dense)
// cmode 0: C[r*ldc + offC + c*sC]
// cmode 1: r=(e,m) packed rows (r=3e+m) -> C[e*512 + 128 + m + 3c]
template <bool VECA>
__global__ void gemm_k(const float* __restrict__ A, int lda, int offA, int sA,
                       const float* __restrict__ B, int ldb,
                       float* __restrict__ C, int ldc, int offC, int sC,
                       int M, int N, int K, float scale, int epi, int cmode) {
    const int BM = 64, BN = 64, BK = 16;
    __shared__ unsigned long long As2[BK][BM];      // duplicated (a,a) pairs
    __shared__ __align__(16) float Bs[BK][BN];

    int tid = threadIdx.x;                  // 256 threads
    int tx = tid & 15, ty = tid >> 4;       // 16 x 16, each 4x4 outputs
    int row0 = blockIdx.x * BM, col0 = blockIdx.y * BN;

    unsigned long long acc[4][2];
#pragma unroll
    for (int i = 0; i < 4; i++) { acc[i][0] = 0ull; acc[i][1] = 0ull; }

    int la_m = tid >> 2;            // 0..63
    int la_k = (tid & 3) * 4;       // 0,4,8,12
    int lb_k = tid >> 4;            // 0..15
    int lb_n = (tid & 15) * 4;

    for (int kt = 0; kt < K; kt += BK) {
        float a0 = 0.f, a1 = 0.f, a2 = 0.f, a3 = 0.f;
        int r = row0 + la_m;
        if (r < M) {
            if (VECA) {
                if (kt + la_k < K) {
                    float4 v4 = *(const float4*)(A + (size_t)r * lda + offA + kt + la_k);
                    a0 = v4.x; a1 = v4.y; a2 = v4.z; a3 = v4.w;
                }
            } else {
                int kb = kt + la_k;
                if (kb + 0 < K) a0 = A[(size_t)r * lda + offA + (kb + 0) * sA];
                if (kb + 1 < K) a1 = A[(size_t)r * lda + offA + (kb + 1) * sA];
                if (kb + 2 < K) a2 = A[(size_t)r * lda + offA + (kb + 2) * sA];
                if (kb + 3 < K) a3 = A[(size_t)r * lda + offA + (kb + 3) * sA];
            }
        }
        As2[la_k + 0][la_m] = pk2(a0);
        As2[la_k + 1][la_m] = pk2(a1);
        As2[la_k + 2][la_m] = pk2(a2);
        As2[la_k + 3][la_m] = pk2(a3);

        int kb = kt + lb_k;
        float4 b4 = make_float4(0.f, 0.f, 0.f, 0.f);
        if (kb < K) b4 = *(const float4*)(B + (size_t)kb * ldb + col0 + lb_n);
        *(float4*)&Bs[lb_k][lb_n] = b4;

        __syncthreads();
#pragma unroll
        for (int kk = 0; kk < BK; kk++) {
            ulonglong2 b01 = *(const ulonglong2*)&Bs[kk][tx * 4];
            unsigned long long av[4];
#pragma unroll
            for (int i = 0; i < 4; i++) av[i] = As2[kk][ty * 4 + i];
#pragma unroll
            for (int i = 0; i < 4; i++) {
                ffma2(acc[i][0], av[i], b01.x);
                ffma2(acc[i][1], av[i], b01.y);
            }
        }
        __syncthreads();
    }

    float cst = (epi == 1) ? gCST : 1.f;
#pragma unroll
    for (int i = 0; i < 4; i++) {
        int r = row0 + ty * 4 + i;
        if (r >= M) continue;
#pragma unroll
        for (int jp = 0; jp < 2; jp++) {
            float2 v = upk(acc[i][jp]);
            int c0 = col0 + tx * 4 + jp * 2;
#pragma unroll
            for (int q = 0; q < 2; q++) {
                float x = ((q == 0) ? v.x : v.y) * scale;
                if (epi == 1) x = x / (1.f + __expf(-x)) * cst;
                int c = c0 + q;
                size_t addr;
                if (cmode == 0) {
                    addr = (size_t)r * ldc + offC + (size_t)c * sC;
                } else {
                    int e = r / 3, m = r - 3 * e;
                    addr = (size_t)e * 512 + 128 + m + 3 * c;
                }
                C[addr] = x;
            }
        }
    }
}

// ---------------- gather + tensor-product elementwise ---------------------------
__global__ void ew_kernel(const void* __restrict__ eidx_raw,
                          const float* __restrict__ eattr) {
    int e = blockIdx.x * 2 + (threadIdx.x >> 7);
    int u = threadIdx.x & 127;
    if (e >= NE) return;

    const int* e32 = (const int*)eidx_raw;
    const long long* e64 = (const long long*)eidx_raw;
    int snd = gIdx64 ? (int)e64[e] : e32[e];
    snd = min(max(snd, 0), NN - 1);

    float y0 = eattr[4 * e + 0];
    float y10 = eattr[4 * e + 1], y11 = eattr[4 * e + 2], y12 = eattr[4 * e + 3];
    const float* T = gT + (size_t)e * 512;
    float wa = T[u], wb = T[128 + u], wc = T[256 + u], wd = T[384 + u];
    float s1 = gS[snd * 128 + u];
    const float* Vp = gV + snd * 384;
    float v0 = Vp[u], v1 = Vp[128 + u], v2 = Vp[256 + u];

    float* SC = gSCAL + (size_t)e * 256;
    SC[u]       = wa * s1 * y0;
    SC[128 + u] = wb * (v0 * y10 + v1 * y11 + v2 * y12) * 0.57735026918962576f;

    float wcs = wc * s1, wdy = wd * y0;
    float* VE = gVEC + (size_t)e * 768;
    VE[u]             = wcs * y10;  VE[128 + u]       = wdy * v0;
    VE[256 + u]       = wcs * y11;  VE[256 + 128 + u] = wdy * v1;
    VE[512 + u]       = wcs * y12;  VE[512 + 128 + u] = wdy * v2;
}

// ---------------- launch ---------------------------------------------------------
extern "C" void kernel_launch(void* const* d_in, const int* in_sizes, int n_in,
                              void* d_out, int out_size) {
    const float*     node_feats = (const float*)d_in[0];
    const void*      edge_index = d_in[1];
    const float*     edge_attrs = (const float*)d_in[2];
    const float*     edge_feats = (const float*)d_in[3];
    const float*     W_up_s     = (const float*)d_in[4];
    const float*     W_up_v     = (const float*)d_in[5];
    const float*     W1         = (const float*)d_in[6];
    const float*     W2         = (const float*)d_in[7];
    const float*     W3         = (const float*)d_in[8];
    const float*     W4         = (const float*)d_in[9];
    const float*     W_out_s    = (const float*)d_in[10];
    const float*     W_out_v    = (const float*)d_in[11];
    float* out = (float*)d_out;

    float *pS, *pV, *pHa, *pHb, *pT, *pSC, *pVE;
    cudaGetSymbolAddress((void**)&pS,  gS);
    cudaGetSymbolAddress((void**)&pV,  gV);
    cudaGetSymbolAddress((void**)&pHa, gHa);
    cudaGetSymbolAddress((void**)&pHb, gHb);
    cudaGetSymbolAddress((void**)&pT,  gT);
    cudaGetSymbolAddress((void**)&pSC, gSCAL);
    cudaGetSymbolAddress((void**)&pVE, gVEC);

    const float inv_m   = 0.08838834764831845f;   // 1/sqrt(128)
    const float inv_8   = 0.35355339059327373f;   // 1/sqrt(8)
    const float inv_64  = 0.125f;                 // 1/sqrt(64)
    const float inv_2m  = 0.0625f;                // 1/sqrt(256)

    cst_kernel<<<1, 256>>>();
    detect_idx_kernel<<<1, 32>>>((const int*)edge_index);

    // node scalar: S = NF[:, :128] @ W_up_s
    gemm_k<true><<<dim3(157, 2), 256>>>(node_feats, 512, 0, 1, W_up_s, 128,
                                        pS, 128, 0, 1, NN, 128, 128, inv_m, 0, 0);
    // node vector (3 strided GEMMs, output layout [n][m][u])
    for (int m = 0; m < 3; m++) {
        gemm_k<false><<<dim3(157, 2), 256>>>(node_feats, 512, 128 + m, 3, W_up_v, 128,
                                             pV, 384, m * 128, 1, NN, 128, 128, inv_m, 0, 0);
    }
    // edge MLP
    gemm_k<true><<<dim3(3125, 1), 256>>>(edge_feats, 8, 0, 1, W1, 64,
                                         pHa, 64, 0, 1, NE, 64, 8, inv_8, 1, 0);
    gemm_k<true><<<dim3(3125, 1), 256>>>(pHa, 64, 0, 1, W2, 64,
                                         pHb, 64, 0, 1, NE, 64, 64, inv_64, 1, 0);
    gemm_k<true><<<dim3(3125, 1), 256>>>(pHb, 64, 0, 1, W3, 64,
                                         pHa, 64, 0, 1, NE, 64, 64, inv_64, 1, 0);
    gemm_k<true><<<dim3(3125, 8), 256>>>(pHa, 64, 0, 1, W4, 512,
                                         pT, 512, 0, 1, NE, 512, 64, inv_64, 0, 0);
    // gather + tensor product
    ew_kernel<<<100000, 256>>>(edge_index, edge_attrs);

    // scalar output: out[:, :128] = SCAL @ W_out_s / 16
    gemm_k<true><<<dim3(3125, 2), 256>>>(pSC, 256, 0, 1, W_out_s, 128,
                                         out, 512, 0, 1, NE, 128, 256, inv_2m, 0, 0);
    // vector output: rows (e,m), custom epilogue into out[:, 128:512]
    gemm_k<true><<<dim3(9375, 2), 256>>>(pVE, 256, 0, 1, W_out_v, 128,
                                         out, 0, 0, 0, 3 * NE, 128, 256, inv_2m, 0, 1);
    (void)in_sizes; (void)n_in; (void)out_size;
}

// round 4
// speedup vs baseline: 1.3596x; 1.3596x over previous
#include <cuda_runtime.h>
#include <cuda_bf16.h>
#include <math.h>
#include <stdint.h>

#define NE 200000
#define NN 10000

// ---------------- scratch ----------------
__device__ float gS[NN * 128];
__device__ float gV[NN * 384];
__device__ float gHa[NE * 64];
__device__ float gHb[NE * 64];
__device__ float gT[(size_t)NE * 512];
__device__ float gSCAL[(size_t)NE * 256];
__device__ float gVEC[(size_t)NE * 768];
__device__ float gCST;
__device__ int   gIdx64;

// ---------------- helpers ----------------
__device__ __forceinline__ unsigned pk_bf2(float x, float y) {
    __nv_bfloat162 t = __floats2bfloat162_rn(x, y);
    return *(unsigned*)&t;
}
__device__ __forceinline__ void mma_bf16(float c[4], const unsigned a[4], const unsigned b[2]) {
    asm volatile("mma.sync.aligned.m16n8k16.row.col.f32.bf16.bf16.f32 "
        "{%0,%1,%2,%3}, {%4,%5,%6,%7}, {%8,%9}, {%0,%1,%2,%3};\n"
        : "+f"(c[0]), "+f"(c[1]), "+f"(c[2]), "+f"(c[3])
        : "r"(a[0]), "r"(a[1]), "r"(a[2]), "r"(a[3]), "r"(b[0]), "r"(b[1]));
}

// ---------------- tensor-core GEMM via mma.sync, split-bf16 --------------------
// C[r][c] = scale * sum_k A[r][k]*B[k][c]; A [M,lda] row-major, B [K,ldb] row-major.
// Block tile 128x64, BK=32, 256 threads (8 warps, each 32x32).
// Requires K % 32 == 0, N multiple of 64 (grid.y covers N/64).
// SILU: silu*CST epilogue. CMODE 1: r=3e+m -> C[e*512+128+m+3c].
template <int SILU, int CMODE>
__global__ __launch_bounds__(256) void mma_gemm(
        const float* __restrict__ A, int lda,
        const float* __restrict__ B, int ldb,
        float* __restrict__ C, int ldc,
        int M, int K, float scale) {
    const int PK = 40;   // smem pitch (elements): conflict-free fragment reads
    __shared__ __align__(16) unsigned short Ah[128][PK];
    __shared__ __align__(16) unsigned short Al[128][PK];
    __shared__ __align__(16) unsigned short Bh2[64][PK];
    __shared__ __align__(16) unsigned short Bl2[64][PK];

    int tid = threadIdx.x;
    int wid = tid >> 5, lane = tid & 31;
    int warp_m = wid & 3, warp_n = wid >> 2;      // 4 x 2 warps
    int g = lane >> 2, tg = lane & 3;
    int row0 = blockIdx.x * 128, col0 = blockIdx.y * 64;
    int am = warp_m * 32, bn = warp_n * 32;

    float acc[2][4][4];
#pragma unroll
    for (int mt = 0; mt < 2; mt++)
#pragma unroll
        for (int nt = 0; nt < 4; nt++)
#pragma unroll
            for (int j = 0; j < 4; j++) acc[mt][nt][j] = 0.f;

    for (int kc = 0; kc < K; kc += 32) {
        // ---- stage A chunk [128 x 32] fp32 -> bf16 hi/lo ----
#pragma unroll
        for (int i = 0; i < 4; i++) {
            int idx = tid + i * 256;          // 0..1023
            int r = idx >> 3, c4 = idx & 7;   // row, float4-col
            int gr = row0 + r;
            float4 v = make_float4(0.f, 0.f, 0.f, 0.f);
            if (gr < M) v = *(const float4*)(A + (size_t)gr * lda + kc + c4 * 4);
            float h0 = __bfloat162float(__float2bfloat16_rn(v.x));
            float h1 = __bfloat162float(__float2bfloat16_rn(v.y));
            float h2 = __bfloat162float(__float2bfloat16_rn(v.z));
            float h3 = __bfloat162float(__float2bfloat16_rn(v.w));
            uint2 hv = make_uint2(pk_bf2(v.x, v.y), pk_bf2(v.z, v.w));
            uint2 lv = make_uint2(pk_bf2(v.x - h0, v.y - h1), pk_bf2(v.z - h2, v.w - h3));
            *(uint2*)&Ah[r][c4 * 4] = hv;
            *(uint2*)&Al[r][c4 * 4] = lv;
        }
        // ---- stage B chunk [32 x 64] -> Bs[n][k] transposed, bf16 hi/lo ----
        {
            int n = tid & 63;
            int k0 = (tid >> 6) * 8;          // 0,8,16,24
            const float* Bp = B + (size_t)(kc + k0) * ldb + col0 + n;
            float vb[8];
#pragma unroll
            for (int j = 0; j < 8; j++) vb[j] = Bp[(size_t)j * ldb];
            unsigned hv[4], lv[4];
#pragma unroll
            for (int j = 0; j < 4; j++) {
                float h0 = __bfloat162float(__float2bfloat16_rn(vb[2 * j]));
                float h1 = __bfloat162float(__float2bfloat16_rn(vb[2 * j + 1]));
                hv[j] = pk_bf2(vb[2 * j], vb[2 * j + 1]);
                lv[j] = pk_bf2(vb[2 * j] - h0, vb[2 * j + 1] - h1);
            }
            *(uint4*)&Bh2[n][k0] = *(uint4*)hv;
            *(uint4*)&Bl2[n][k0] = *(uint4*)lv;
        }
        __syncthreads();

#pragma unroll
        for (int ks = 0; ks < 2; ks++) {
            unsigned ah[2][4], al2[2][4], bh[4][2], bl[4][2];
#pragma unroll
            for (int mt = 0; mt < 2; mt++) {
                const unsigned short* p = &Ah[am + mt * 16 + g][ks * 16 + tg * 2];
                const unsigned short* q = &Al[am + mt * 16 + g][ks * 16 + tg * 2];
                ah[mt][0] = *(const unsigned*)p;
                ah[mt][1] = *(const unsigned*)(p + 8 * PK);
                ah[mt][2] = *(const unsigned*)(p + 8);
                ah[mt][3] = *(const unsigned*)(p + 8 * PK + 8);
                al2[mt][0] = *(const unsigned*)q;
                al2[mt][1] = *(const unsigned*)(q + 8 * PK);
                al2[mt][2] = *(const unsigned*)(q + 8);
                al2[mt][3] = *(const unsigned*)(q + 8 * PK + 8);
            }
#pragma unroll
            for (int nt = 0; nt < 4; nt++) {
                const unsigned short* p = &Bh2[bn + nt * 8 + g][ks * 16 + tg * 2];
                const unsigned short* q = &Bl2[bn + nt * 8 + g][ks * 16 + tg * 2];
                bh[nt][0] = *(const unsigned*)p;
                bh[nt][1] = *(const unsigned*)(p + 8);
                bl[nt][0] = *(const unsigned*)q;
                bl[nt][1] = *(const unsigned*)(q + 8);
            }
#pragma unroll
            for (int mt = 0; mt < 2; mt++)
#pragma unroll
                for (int nt = 0; nt < 4; nt++) {
                    mma_bf16(acc[mt][nt], ah[mt], bh[nt]);
                    mma_bf16(acc[mt][nt], ah[mt], bl[nt]);
                    mma_bf16(acc[mt][nt], al2[mt], bh[nt]);
                }
        }
        __syncthreads();
    }

    // ---- epilogue ----
    float cst = SILU ? gCST : 1.f;
#pragma unroll
    for (int mt = 0; mt < 2; mt++) {
        int r1 = row0 + am + mt * 16 + g;
        int r2 = r1 + 8;
#pragma unroll
        for (int nt = 0; nt < 4; nt++) {
            int cc = col0 + bn + nt * 8 + tg * 2;
            float x0 = acc[mt][nt][0] * scale, x1 = acc[mt][nt][1] * scale;
            float x2 = acc[mt][nt][2] * scale, x3 = acc[mt][nt][3] * scale;
            if (SILU) {
                x0 = x0 / (1.f + __expf(-x0)) * cst;
                x1 = x1 / (1.f + __expf(-x1)) * cst;
                x2 = x2 / (1.f + __expf(-x2)) * cst;
                x3 = x3 / (1.f + __expf(-x3)) * cst;
            }
            if (CMODE == 0) {
                if (r1 < M) { float2 o = make_float2(x0, x1); *(float2*)&C[(size_t)r1 * ldc + cc] = o; }
                if (r2 < M) { float2 o = make_float2(x2, x3); *(float2*)&C[(size_t)r2 * ldc + cc] = o; }
            } else {
                if (r1 < M) {
                    int e = r1 / 3, m = r1 - 3 * e;
                    C[(size_t)e * 512 + 128 + m + 3 * cc] = x0;
                    C[(size_t)e * 512 + 128 + m + 3 * (cc + 1)] = x1;
                }
                if (r2 < M) {
                    int e = r2 / 3, m = r2 - 3 * e;
                    C[(size_t)e * 512 + 128 + m + 3 * cc] = x2;
                    C[(size_t)e * 512 + 128 + m + 3 * (cc + 1)] = x3;
                }
            }
        }
    }
}

// ---------------- idx dtype detector ----------------
__global__ void detect_idx_kernel(const int* __restrict__ idx32) {
    if (threadIdx.x == 0) {
        int any = 0;
        for (int i = 1; i < 256; i += 2) any |= (idx32[i] != 0);
        gIdx64 = (any == 0) ? 1 : 0;
    }
}

// ---------------- SILU_CST ----------------
__global__ void cst_kernel() {
    __shared__ double red[256];
    int t = threadIdx.x;
    double acc = 0.0;
    for (int j = t; j <= 200000; j += 256) {
        double z = -12.0 + 24.0 * ((double)j / 200000.0);
        double pdf = exp(-0.5 * z * z) * 0.39894228040143267794;
        double s = z / (1.0 + exp(-z));
        double f = s * s * pdf;
        if (j == 0 || j == 200000) f *= 0.5;
        acc += f;
    }
    red[t] = acc;
    __syncthreads();
    for (int o = 128; o > 0; o >>= 1) {
        if (t < o) red[t] += red[t + o];
        __syncthreads();
    }
    if (t == 0) gCST = (float)(1.0 / sqrt(red[0] * (24.0 / 200000.0)));
}

// ---------------- SIMT GEMM (small ops) ----------------
__device__ __forceinline__ unsigned long long pk2(float x) {
    unsigned long long r; unsigned u = __float_as_uint(x);
    asm("mov.b64 %0, {%1, %1};" : "=l"(r) : "r"(u));
    return r;
}
__device__ __forceinline__ void ffma2(unsigned long long& d, unsigned long long a,
                                      unsigned long long b) {
    asm("fma.rn.f32x2 %0, %1, %2, %0;" : "+l"(d) : "l"(a), "l"(b));
}
__device__ __forceinline__ float2 upk(unsigned long long v) {
    unsigned lo, hi;
    asm("mov.b64 {%0, %1}, %2;" : "=r"(lo), "=r"(hi) : "l"(v));
    return make_float2(__uint_as_float(lo), __uint_as_float(hi));
}

template <bool VECA>
__global__ void gemm_k(const float* __restrict__ A, int lda, int offA, int sA,
                       const float* __restrict__ B, int ldb,
                       float* __restrict__ C, int ldc, int offC,
                       int M, int N, int K, float scale, int epi) {
    const int BM = 64, BN = 64, BK = 16;
    __shared__ unsigned long long As2[BK][BM];
    __shared__ __align__(16) float Bs[BK][BN];
    int tid = threadIdx.x;
    int tx = tid & 15, ty = tid >> 4;
    int row0 = blockIdx.x * BM, col0 = blockIdx.y * BN;
    unsigned long long acc[4][2];
#pragma unroll
    for (int i = 0; i < 4; i++) { acc[i][0] = 0ull; acc[i][1] = 0ull; }
    int la_m = tid >> 2, la_k = (tid & 3) * 4;
    int lb_k = tid >> 4, lb_n = (tid & 15) * 4;
    for (int kt = 0; kt < K; kt += BK) {
        float a0 = 0.f, a1 = 0.f, a2 = 0.f, a3 = 0.f;
        int r = row0 + la_m;
        if (r < M) {
            if (VECA) {
                if (kt + la_k < K) {
                    float4 v4 = *(const float4*)(A + (size_t)r * lda + offA + kt + la_k);
                    a0 = v4.x; a1 = v4.y; a2 = v4.z; a3 = v4.w;
                }
            } else {
                int kb = kt + la_k;
                if (kb + 0 < K) a0 = A[(size_t)r * lda + offA + (kb + 0) * sA];
                if (kb + 1 < K) a1 = A[(size_t)r * lda + offA + (kb + 1) * sA];
                if (kb + 2 < K) a2 = A[(size_t)r * lda + offA + (kb + 2) * sA];
                if (kb + 3 < K) a3 = A[(size_t)r * lda + offA + (kb + 3) * sA];
            }
        }
        As2[la_k + 0][la_m] = pk2(a0);
        As2[la_k + 1][la_m] = pk2(a1);
        As2[la_k + 2][la_m] = pk2(a2);
        As2[la_k + 3][la_m] = pk2(a3);
        int kb = kt + lb_k;
        float4 b4 = make_float4(0.f, 0.f, 0.f, 0.f);
        if (kb < K) b4 = *(const float4*)(B + (size_t)kb * ldb + col0 + lb_n);
        *(float4*)&Bs[lb_k][lb_n] = b4;
        __syncthreads();
#pragma unroll
        for (int kk = 0; kk < BK; kk++) {
            ulonglong2 b01 = *(const ulonglong2*)&Bs[kk][tx * 4];
            unsigned long long av[4];
#pragma unroll
            for (int i = 0; i < 4; i++) av[i] = As2[kk][ty * 4 + i];
#pragma unroll
            for (int i = 0; i < 4; i++) {
                ffma2(acc[i][0], av[i], b01.x);
                ffma2(acc[i][1], av[i], b01.y);
            }
        }
        __syncthreads();
    }
    float cst = (epi == 1) ? gCST : 1.f;
#pragma unroll
    for (int i = 0; i < 4; i++) {
        int r = row0 + ty * 4 + i;
        if (r >= M) continue;
#pragma unroll
        for (int jp = 0; jp < 2; jp++) {
            float2 v = upk(acc[i][jp]);
            int c0 = col0 + tx * 4 + jp * 2;
#pragma unroll
            for (int q = 0; q < 2; q++) {
                float x = ((q == 0) ? v.x : v.y) * scale;
                if (epi == 1) x = x / (1.f + __expf(-x)) * cst;
                C[(size_t)r * ldc + offC + c0 + q] = x;
            }
        }
    }
}

// ---------------- gather + tensor product ----------------
__global__ void ew_kernel(const void* __restrict__ eidx_raw,
                          const float* __restrict__ eattr) {
    int e = blockIdx.x * 2 + (threadIdx.x >> 7);
    int u = threadIdx.x & 127;
    if (e >= NE) return;
    const int* e32 = (const int*)eidx_raw;
    const long long* e64 = (const long long*)eidx_raw;
    int snd = gIdx64 ? (int)e64[e] : e32[e];
    snd = min(max(snd, 0), NN - 1);
    float y0 = eattr[4 * e + 0];
    float y10 = eattr[4 * e + 1], y11 = eattr[4 * e + 2], y12 = eattr[4 * e + 3];
    const float* T = gT + (size_t)e * 512;
    float wa = T[u], wb = T[128 + u], wc = T[256 + u], wd = T[384 + u];
    float s1 = gS[snd * 128 + u];
    const float* Vp = gV + snd * 384;
    float v0 = Vp[u], v1 = Vp[128 + u], v2 = Vp[256 + u];
    float* SC = gSCAL + (size_t)e * 256;
    SC[u]       = wa * s1 * y0;
    SC[128 + u] = wb * (v0 * y10 + v1 * y11 + v2 * y12) * 0.57735026918962576f;
    float wcs = wc * s1, wdy = wd * y0;
    float* VE = gVEC + (size_t)e * 768;
    VE[u]             = wcs * y10;  VE[128 + u]       = wdy * v0;
    VE[256 + u]       = wcs * y11;  VE[256 + 128 + u] = wdy * v1;
    VE[512 + u]       = wcs * y12;  VE[512 + 128 + u] = wdy * v2;
}

// ---------------- launch ----------------
extern "C" void kernel_launch(void* const* d_in, const int* in_sizes, int n_in,
                              void* d_out, int out_size) {
    const float* node_feats = (const float*)d_in[0];
    const void*  edge_index = d_in[1];
    const float* edge_attrs = (const float*)d_in[2];
    const float* edge_feats = (const float*)d_in[3];
    const float* W_up_s     = (const float*)d_in[4];
    const float* W_up_v     = (const float*)d_in[5];
    const float* W1         = (const float*)d_in[6];
    const float* W2         = (const float*)d_in[7];
    const float* W3         = (const float*)d_in[8];
    const float* W4         = (const float*)d_in[9];
    const float* W_out_s    = (const float*)d_in[10];
    const float* W_out_v    = (const float*)d_in[11];
    float* out = (float*)d_out;

    float *pS, *pV, *pHa, *pHb, *pT, *pSC, *pVE;
    cudaGetSymbolAddress((void**)&pS,  gS);
    cudaGetSymbolAddress((void**)&pV,  gV);
    cudaGetSymbolAddress((void**)&pHa, gHa);
    cudaGetSymbolAddress((void**)&pHb, gHb);
    cudaGetSymbolAddress((void**)&pT,  gT);
    cudaGetSymbolAddress((void**)&pSC, gSCAL);
    cudaGetSymbolAddress((void**)&pVE, gVEC);

    const float inv_m  = 0.08838834764831845f;
    const float inv_8  = 0.35355339059327373f;
    const float inv_64 = 0.125f;
    const float inv_2m = 0.0625f;

    cst_kernel<<<1, 256>>>();
    detect_idx_kernel<<<1, 32>>>((const int*)edge_index);

    // node up-projections (SIMT, small)
    gemm_k<true><<<dim3(157, 2), 256>>>(node_feats, 512, 0, 1, W_up_s, 128,
                                        pS, 128, 0, NN, 128, 128, inv_m, 0);
    for (int m = 0; m < 3; m++)
        gemm_k<false><<<dim3(157, 2), 256>>>(node_feats, 512, 128 + m, 3, W_up_v, 128,
                                             pV, 384, m * 128, NN, 128, 128, inv_m, 0);

    // MLP1 (K=8, SIMT)
    gemm_k<true><<<dim3(3125, 1), 256>>>(edge_feats, 8, 0, 1, W1, 64,
                                         pHa, 64, 0, NE, 64, 8, inv_8, 1);
    // MLP2, MLP3 (tensor, silu)
    mma_gemm<1, 0><<<dim3(1563, 1), 256>>>(pHa, 64, W2, 64, pHb, 64, NE, 64, inv_64);
    mma_gemm<1, 0><<<dim3(1563, 1), 256>>>(pHb, 64, W3, 64, pHa, 64, NE, 64, inv_64);
    // W4 (tensor)
    mma_gemm<0, 0><<<dim3(1563, 8), 256>>>(pHa, 64, W4, 512, pT, 512, NE, 64, inv_64);

    // gather + tensor product
    ew_kernel<<<100000, 256>>>(edge_index, edge_attrs);

    // output GEMMs (tensor)
    mma_gemm<0, 0><<<dim3(1563, 2), 256>>>(pSC, 256, W_out_s, 128, out, 512, NE, 256, inv_2m);
    mma_gemm<0, 1><<<dim3(4688, 2), 256>>>(pVE, 256, W_out_v, 128, out, 0, 3 * NE, 256, inv_2m);
    (void)in_sizes; (void)n_in; (void)out_size;
}

// round 5
// speedup vs baseline: 1.4518x; 1.0678x over previous
#include <cuda_runtime.h>
#include <cuda_bf16.h>
#include <math.h>
#include <stdint.h>

#define NE 200000
#define NN 10000

// ---------------- scratch ----------------
__device__ float gS[NN * 128];
__device__ float gV[NN * 384];
__device__ float gHa[NE * 64];
__device__ float gHb[NE * 64];
__device__ float gT[(size_t)NE * 512];
__device__ float gSCAL[(size_t)NE * 256];
__device__ float gVEC[(size_t)NE * 768];
__device__ float gCST;
__device__ int   gIdx64;

// ---------------- helpers ----------------
__device__ __forceinline__ uint32_t smem_u32(const void* p) {
    uint32_t a;
    asm("{ .reg .u64 t; cvta.to.shared.u64 t, %1; cvt.u32.u64 %0, t; }" : "=r"(a) : "l"(p));
    return a;
}
__device__ __forceinline__ unsigned pk_bf2(float x, float y) {
    __nv_bfloat162 t = __floats2bfloat162_rn(x, y);
    return *(unsigned*)&t;
}
__device__ __forceinline__ void mma_bf16(float c[4], const unsigned a[4], const unsigned b[2]) {
    asm volatile("mma.sync.aligned.m16n8k16.row.col.f32.bf16.bf16.f32 "
        "{%0,%1,%2,%3}, {%4,%5,%6,%7}, {%8,%9}, {%0,%1,%2,%3};\n"
        : "+f"(c[0]), "+f"(c[1]), "+f"(c[2]), "+f"(c[3])
        : "r"(a[0]), "r"(a[1]), "r"(a[2]), "r"(a[3]), "r"(b[0]), "r"(b[1]));
}
__device__ __forceinline__ void ldsm4(unsigned r[4], uint32_t addr) {
    asm volatile("ldmatrix.sync.aligned.m8n8.x4.shared.b16 {%0,%1,%2,%3}, [%4];"
        : "=r"(r[0]), "=r"(r[1]), "=r"(r[2]), "=r"(r[3]) : "r"(addr));
}

// ---------------- tensor-core GEMM: ldmatrix + pipelined loads -----------------
// C[r][c] = scale * sum_k A[r][k]*B[k][c]; A [M,lda] row-major, B [K,ldb] row-major.
// Block tile 128x64, BK=32, 256 threads (8 warps, 4x2, each 32x32).
// K % 32 == 0, grid.y covers N/64. SILU: silu*CST. CMODE 1: r=3e+m interleave.
template <int SILU, int CMODE>
__global__ __launch_bounds__(256, 2) void mma_gemm(
        const float* __restrict__ A, int lda,
        const float* __restrict__ B, int ldb,
        float* __restrict__ C, int ldc,
        int M, int K, float scale) {
    const int PK = 40;   // pitch: 80B rows -> 16B-aligned, LDSM conflict-free
    __shared__ __align__(16) unsigned short Ah[128][PK];
    __shared__ __align__(16) unsigned short Al[128][PK];
    __shared__ __align__(16) unsigned short Bh2[64][PK];
    __shared__ __align__(16) unsigned short Bl2[64][PK];

    int tid = threadIdx.x;
    int wid = tid >> 5, lane = tid & 31;
    int warp_m = wid & 3, warp_n = wid >> 2;
    int g = lane >> 2, tg = lane & 3;
    int row0 = blockIdx.x * 128, col0 = blockIdx.y * 64;
    int am = warp_m * 32, bn = warp_n * 32;

    // ldmatrix lane->address mapping
    int arow = (lane & 7) + ((lane >> 3) & 1) * 8;
    int acol = (lane >> 4) * 8;
    uint32_t aAddrH = smem_u32(&Ah[am + arow][acol]);
    uint32_t aAddrL = smem_u32(&Al[am + arow][acol]);
    int brow = (lane & 7) + ((lane >> 4) & 1) * 8;
    int bcol = ((lane >> 3) & 1) * 8;
    uint32_t bAddrH = smem_u32(&Bh2[bn + brow][bcol]);
    uint32_t bAddrL = smem_u32(&Bl2[bn + brow][bcol]);

    float acc[2][4][4];
#pragma unroll
    for (int mt = 0; mt < 2; mt++)
#pragma unroll
        for (int nt = 0; nt < 4; nt++)
#pragma unroll
            for (int j = 0; j < 4; j++) acc[mt][nt][j] = 0.f;

    // staging registers
    float4 aS[4];
    float  bS[8];
    int sAr[4];
    {
#pragma unroll
        for (int i = 0; i < 4; i++) {
            int idx = tid + i * 256;
            sAr[i] = idx >> 3;
        }
    }
    int sAc = (tid & 7) * 4;          // col within chunk for A staging (same all i)
    int sBn = tid & 63;
    int sBk = (tid >> 6) * 8;

    int nchunks = K / 32;
    // prologue: load chunk 0
#pragma unroll
    for (int i = 0; i < 4; i++) {
        int gr = row0 + sAr[i];
        aS[i] = (gr < M) ? *(const float4*)(A + (size_t)gr * lda + 0 + sAc)
                         : make_float4(0.f, 0.f, 0.f, 0.f);
    }
    {
        const float* Bp = B + (size_t)sBk * ldb + col0 + sBn;
#pragma unroll
        for (int j = 0; j < 8; j++) bS[j] = Bp[(size_t)j * ldb];
    }

    for (int ci = 0; ci < nchunks; ci++) {
        // ---- convert staged regs -> smem (bf16 hi/lo) ----
#pragma unroll
        for (int i = 0; i < 4; i++) {
            float4 v = aS[i];
            float h0 = __bfloat162float(__float2bfloat16_rn(v.x));
            float h1 = __bfloat162float(__float2bfloat16_rn(v.y));
            float h2 = __bfloat162float(__float2bfloat16_rn(v.z));
            float h3 = __bfloat162float(__float2bfloat16_rn(v.w));
            *(uint2*)&Ah[sAr[i]][sAc] = make_uint2(pk_bf2(v.x, v.y), pk_bf2(v.z, v.w));
            *(uint2*)&Al[sAr[i]][sAc] =
                make_uint2(pk_bf2(v.x - h0, v.y - h1), pk_bf2(v.z - h2, v.w - h3));
        }
        {
            unsigned hv[4], lv[4];
#pragma unroll
            for (int j = 0; j < 4; j++) {
                float h0 = __bfloat162float(__float2bfloat16_rn(bS[2 * j]));
                float h1 = __bfloat162float(__float2bfloat16_rn(bS[2 * j + 1]));
                hv[j] = pk_bf2(bS[2 * j], bS[2 * j + 1]);
                lv[j] = pk_bf2(bS[2 * j] - h0, bS[2 * j + 1] - h1);
            }
            *(uint4*)&Bh2[sBn][sBk] = *(uint4*)hv;
            *(uint4*)&Bl2[sBn][sBk] = *(uint4*)lv;
        }
        __syncthreads();

        // ---- prefetch next chunk (overlaps with MMA below) ----
        if (ci + 1 < nchunks) {
            int kn = (ci + 1) * 32;
#pragma unroll
            for (int i = 0; i < 4; i++) {
                int gr = row0 + sAr[i];
                aS[i] = (gr < M) ? *(const float4*)(A + (size_t)gr * lda + kn + sAc)
                                 : make_float4(0.f, 0.f, 0.f, 0.f);
            }
            const float* Bp = B + (size_t)(kn + sBk) * ldb + col0 + sBn;
#pragma unroll
            for (int j = 0; j < 8; j++) bS[j] = Bp[(size_t)j * ldb];
        }

        // ---- MMA on current chunk ----
#pragma unroll
        for (int ks = 0; ks < 2; ks++) {
            unsigned ah[2][4], al[2][4], bh[2][4], bl[2][4];
#pragma unroll
            for (int mt = 0; mt < 2; mt++) {
                ldsm4(ah[mt], aAddrH + mt * (16 * PK * 2) + ks * 32);
                ldsm4(al[mt], aAddrL + mt * (16 * PK * 2) + ks * 32);
            }
#pragma unroll
            for (int np = 0; np < 2; np++) {
                ldsm4(bh[np], bAddrH + np * (16 * PK * 2) + ks * 32);
                ldsm4(bl[np], bAddrL + np * (16 * PK * 2) + ks * 32);
            }
#pragma unroll
            for (int mt = 0; mt < 2; mt++)
#pragma unroll
                for (int nt = 0; nt < 4; nt++) {
                    const unsigned* bhf = &bh[nt >> 1][(nt & 1) * 2];
                    const unsigned* blf = &bl[nt >> 1][(nt & 1) * 2];
                    mma_bf16(acc[mt][nt], ah[mt], bhf);
                    mma_bf16(acc[mt][nt], ah[mt], blf);
                    mma_bf16(acc[mt][nt], al[mt], bhf);
                }
        }
        __syncthreads();
    }

    // ---- epilogue ----
    float cst = SILU ? gCST : 1.f;
#pragma unroll
    for (int mt = 0; mt < 2; mt++) {
        int r1 = row0 + am + mt * 16 + g;
        int r2 = r1 + 8;
#pragma unroll
        for (int nt = 0; nt < 4; nt++) {
            int cc = col0 + bn + nt * 8 + tg * 2;
            float x0 = acc[mt][nt][0] * scale, x1 = acc[mt][nt][1] * scale;
            float x2 = acc[mt][nt][2] * scale, x3 = acc[mt][nt][3] * scale;
            if (SILU) {
                x0 = x0 / (1.f + __expf(-x0)) * cst;
                x1 = x1 / (1.f + __expf(-x1)) * cst;
                x2 = x2 / (1.f + __expf(-x2)) * cst;
                x3 = x3 / (1.f + __expf(-x3)) * cst;
            }
            if (CMODE == 0) {
                if (r1 < M) { float2 o = make_float2(x0, x1); *(float2*)&C[(size_t)r1 * ldc + cc] = o; }
                if (r2 < M) { float2 o = make_float2(x2, x3); *(float2*)&C[(size_t)r2 * ldc + cc] = o; }
            } else {
                if (r1 < M) {
                    int e = r1 / 3, m = r1 - 3 * e;
                    C[(size_t)e * 512 + 128 + m + 3 * cc] = x0;
                    C[(size_t)e * 512 + 128 + m + 3 * (cc + 1)] = x1;
                }
                if (r2 < M) {
                    int e = r2 / 3, m = r2 - 3 * e;
                    C[(size_t)e * 512 + 128 + m + 3 * cc] = x2;
                    C[(size_t)e * 512 + 128 + m + 3 * (cc + 1)] = x3;
                }
            }
        }
    }
}

// ---------------- idx dtype detector ----------------
__global__ void detect_idx_kernel(const int* __restrict__ idx32) {
    if (threadIdx.x == 0) {
        int any = 0;
        for (int i = 1; i < 256; i += 2) any |= (idx32[i] != 0);
        gIdx64 = (any == 0) ? 1 : 0;
    }
}

// ---------------- SILU_CST ----------------
__global__ void cst_kernel() {
    __shared__ double red[256];
    int t = threadIdx.x;
    double acc = 0.0;
    for (int j = t; j <= 200000; j += 256) {
        double z = -12.0 + 24.0 * ((double)j / 200000.0);
        double pdf = exp(-0.5 * z * z) * 0.39894228040143267794;
        double s = z / (1.0 + exp(-z));
        double f = s * s * pdf;
        if (j == 0 || j == 200000) f *= 0.5;
        acc += f;
    }
    red[t] = acc;
    __syncthreads();
    for (int o = 128; o > 0; o >>= 1) {
        if (t < o) red[t] += red[t + o];
        __syncthreads();
    }
    if (t == 0) gCST = (float)(1.0 / sqrt(red[0] * (24.0 / 200000.0)));
}

// ---------------- SIMT GEMM (small ops) ----------------
__device__ __forceinline__ unsigned long long pk2(float x) {
    unsigned long long r; unsigned u = __float_as_uint(x);
    asm("mov.b64 %0, {%1, %1};" : "=l"(r) : "r"(u));
    return r;
}
__device__ __forceinline__ void ffma2(unsigned long long& d, unsigned long long a,
                                      unsigned long long b) {
    asm("fma.rn.f32x2 %0, %1, %2, %0;" : "+l"(d) : "l"(a), "l"(b));
}
__device__ __forceinline__ float2 upk(unsigned long long v) {
    unsigned lo, hi;
    asm("mov.b64 {%0, %1}, %2;" : "=r"(lo), "=r"(hi) : "l"(v));
    return make_float2(__uint_as_float(lo), __uint_as_float(hi));
}

template <bool VECA>
__global__ void gemm_k(const float* __restrict__ A, int lda, int offA, int sA,
                       const float* __restrict__ B, int ldb,
                       float* __restrict__ C, int ldc, int offC,
                       int M, int N, int K, float scale, int epi) {
    const int BM = 64, BN = 64, BK = 16;
    __shared__ unsigned long long As2[BK][BM];
    __shared__ __align__(16) float Bs[BK][BN];
    int tid = threadIdx.x;
    int tx = tid & 15, ty = tid >> 4;
    int row0 = blockIdx.x * BM, col0 = blockIdx.y * BN;
    unsigned long long acc[4][2];
#pragma unroll
    for (int i = 0; i < 4; i++) { acc[i][0] = 0ull; acc[i][1] = 0ull; }
    int la_m = tid >> 2, la_k = (tid & 3) * 4;
    int lb_k = tid >> 4, lb_n = (tid & 15) * 4;
    for (int kt = 0; kt < K; kt += BK) {
        float a0 = 0.f, a1 = 0.f, a2 = 0.f, a3 = 0.f;
        int r = row0 + la_m;
        if (r < M) {
            if (VECA) {
                if (kt + la_k < K) {
                    float4 v4 = *(const float4*)(A + (size_t)r * lda + offA + kt + la_k);
                    a0 = v4.x; a1 = v4.y; a2 = v4.z; a3 = v4.w;
                }
            } else {
                int kb = kt + la_k;
                if (kb + 0 < K) a0 = A[(size_t)r * lda + offA + (kb + 0) * sA];
                if (kb + 1 < K) a1 = A[(size_t)r * lda + offA + (kb + 1) * sA];
                if (kb + 2 < K) a2 = A[(size_t)r * lda + offA + (kb + 2) * sA];
                if (kb + 3 < K) a3 = A[(size_t)r * lda + offA + (kb + 3) * sA];
            }
        }
        As2[la_k + 0][la_m] = pk2(a0);
        As2[la_k + 1][la_m] = pk2(a1);
        As2[la_k + 2][la_m] = pk2(a2);
        As2[la_k + 3][la_m] = pk2(a3);
        int kb = kt + lb_k;
        float4 b4 = make_float4(0.f, 0.f, 0.f, 0.f);
        if (kb < K) b4 = *(const float4*)(B + (size_t)kb * ldb + col0 + lb_n);
        *(float4*)&Bs[lb_k][lb_n] = b4;
        __syncthreads();
#pragma unroll
        for (int kk = 0; kk < BK; kk++) {
            ulonglong2 b01 = *(const ulonglong2*)&Bs[kk][tx * 4];
            unsigned long long av[4];
#pragma unroll
            for (int i = 0; i < 4; i++) av[i] = As2[kk][ty * 4 + i];
#pragma unroll
            for (int i = 0; i < 4; i++) {
                ffma2(acc[i][0], av[i], b01.x);
                ffma2(acc[i][1], av[i], b01.y);
            }
        }
        __syncthreads();
    }
    float cst = (epi == 1) ? gCST : 1.f;
#pragma unroll
    for (int i = 0; i < 4; i++) {
        int r = row0 + ty * 4 + i;
        if (r >= M) continue;
#pragma unroll
        for (int jp = 0; jp < 2; jp++) {
            float2 v = upk(acc[i][jp]);
            int c0 = col0 + tx * 4 + jp * 2;
#pragma unroll
            for (int q = 0; q < 2; q++) {
                float x = ((q == 0) ? v.x : v.y) * scale;
                if (epi == 1) x = x / (1.f + __expf(-x)) * cst;
                C[(size_t)r * ldc + offC + c0 + q] = x;
            }
        }
    }
}

// ---------------- gather + tensor product ----------------
__global__ void ew_kernel(const void* __restrict__ eidx_raw,
                          const float* __restrict__ eattr) {
    int e = blockIdx.x * 2 + (threadIdx.x >> 7);
    int u = threadIdx.x & 127;
    if (e >= NE) return;
    const int* e32 = (const int*)eidx_raw;
    const long long* e64 = (const long long*)eidx_raw;
    int snd = gIdx64 ? (int)e64[e] : e32[e];
    snd = min(max(snd, 0), NN - 1);
    float y0 = eattr[4 * e + 0];
    float y10 = eattr[4 * e + 1], y11 = eattr[4 * e + 2], y12 = eattr[4 * e + 3];
    const float* T = gT + (size_t)e * 512;
    float wa = T[u], wb = T[128 + u], wc = T[256 + u], wd = T[384 + u];
    float s1 = gS[snd * 128 + u];
    const float* Vp = gV + snd * 384;
    float v0 = Vp[u], v1 = Vp[128 + u], v2 = Vp[256 + u];
    float* SC = gSCAL + (size_t)e * 256;
    SC[u]       = wa * s1 * y0;
    SC[128 + u] = wb * (v0 * y10 + v1 * y11 + v2 * y12) * 0.57735026918962576f;
    float wcs = wc * s1, wdy = wd * y0;
    float* VE = gVEC + (size_t)e * 768;
    VE[u]             = wcs * y10;  VE[128 + u]       = wdy * v0;
    VE[256 + u]       = wcs * y11;  VE[256 + 128 + u] = wdy * v1;
    VE[512 + u]       = wcs * y12;  VE[512 + 128 + u] = wdy * v2;
}

// ---------------- launch ----------------
extern "C" void kernel_launch(void* const* d_in, const int* in_sizes, int n_in,
                              void* d_out, int out_size) {
    const float* node_feats = (const float*)d_in[0];
    const void*  edge_index = d_in[1];
    const float* edge_attrs = (const float*)d_in[2];
    const float* edge_feats = (const float*)d_in[3];
    const float* W_up_s     = (const float*)d_in[4];
    const float* W_up_v     = (const float*)d_in[5];
    const float* W1         = (const float*)d_in[6];
    const float* W2         = (const float*)d_in[7];
    const float* W3         = (const float*)d_in[8];
    const float* W4         = (const float*)d_in[9];
    const float* W_out_s    = (const float*)d_in[10];
    const float* W_out_v    = (const float*)d_in[11];
    float* out = (float*)d_out;

    float *pS, *pV, *pHa, *pHb, *pT, *pSC, *pVE;
    cudaGetSymbolAddress((void**)&pS,  gS);
    cudaGetSymbolAddress((void**)&pV,  gV);
    cudaGetSymbolAddress((void**)&pHa, gHa);
    cudaGetSymbolAddress((void**)&pHb, gHb);
    cudaGetSymbolAddress((void**)&pT,  gT);
    cudaGetSymbolAddress((void**)&pSC, gSCAL);
    cudaGetSymbolAddress((void**)&pVE, gVEC);

    const float inv_m  = 0.08838834764831845f;
    const float inv_8  = 0.35355339059327373f;
    const float inv_64 = 0.125f;
    const float inv_2m = 0.0625f;

    cst_kernel<<<1, 256>>>();
    detect_idx_kernel<<<1, 32>>>((const int*)edge_index);

    // node up-projections (SIMT, small)
    gemm_k<true><<<dim3(157, 2), 256>>>(node_feats, 512, 0, 1, W_up_s, 128,
                                        pS, 128, 0, NN, 128, 128, inv_m, 0);
    for (int m = 0; m < 3; m++)
        gemm_k<false><<<dim3(157, 2), 256>>>(node_feats, 512, 128 + m, 3, W_up_v, 128,
                                             pV, 384, m * 128, NN, 128, 128, inv_m, 0);

    // MLP1 (K=8, SIMT)
    gemm_k<true><<<dim3(3125, 1), 256>>>(edge_feats, 8, 0, 1, W1, 64,
                                         pHa, 64, 0, NE, 64, 8, inv_8, 1);
    // MLP2, MLP3 (tensor, silu)
    mma_gemm<1, 0><<<dim3(1563, 1), 256>>>(pHa, 64, W2, 64, pHb, 64, NE, 64, inv_64);
    mma_gemm<1, 0><<<dim3(1563, 1), 256>>>(pHb, 64, W3, 64, pHa, 64, NE, 64, inv_64);
    // W4 (tensor)
    mma_gemm<0, 0><<<dim3(1563, 8), 256>>>(pHa, 64, W4, 512, pT, 512, NE, 64, inv_64);

    // gather + tensor product
    ew_kernel<<<100000, 256>>>(edge_index, edge_attrs);

    // output GEMMs (tensor)
    mma_gemm<0, 0><<<dim3(1563, 2), 256>>>(pSC, 256, W_out_s, 128, out, 512, NE, 256, inv_2m);
    mma_gemm<0, 1><<<dim3(4688, 2), 256>>>(pVE, 256, W_out_v, 128, out, 0, 3 * NE, 256, inv_2m);
    (void)in_sizes; (void)n_in; (void)out_size;
}